// round 16
// baseline (speedup 1.0000x reference)
#include <cuda_runtime.h>
#include <cuda_bf16.h>
#include <math.h>
#include <stdint.h>

// Problem constants
#define T_  2
#define B_  16
#define C_  256
#define N_  4096
#define NH_ 8
#define D_  32

constexpr int TSTR = B_ * C_ * N_;
constexpr int SZ   = T_ * TSTR;

// ---------------------------------------------------------------------------
// Scratch (device globals)
// ---------------------------------------------------------------------------
__device__ uint4 g_xt8_4[SZ / 16];           // int8 xs transposed [t,b][n][c]
__device__ uint4 g_st8_4[SZ / 16];           // int8 attn spikes transposed [t,b][n][c]
__device__ uint4 g_whi4[4 * 65536 / 8];      // bf16 W_hi {q,k,v,p}
__device__ uint4 g_wlo4[4 * 65536 / 8];      // bf16 W_lo
__device__ float g_kv[T_ * B_ * NH_ * D_ * D_];
__device__ uint32_t g_qpk[32 * N_ * 8];      // q bits packed along channel
__device__ uint32_t g_kpk[32 * C_ * 128];    // k bits packed along n
__device__ uint32_t g_vpk[32 * C_ * 128];    // v bits packed along n

// ---------------------------------------------------------------------------
// PTX helpers (arch-agnostic)
// ---------------------------------------------------------------------------
__device__ __forceinline__ uint32_t smem_u32(const void* p) {
    uint32_t a;
    asm("{ .reg .u64 t; cvta.to.shared.u64 t, %1; cvt.u32.u64 %0, t; }"
        : "=r"(a) : "l"(p));
    return a;
}
__device__ __forceinline__ void cp16(uint32_t dst, const void* src) {
    asm volatile("cp.async.ca.shared.global [%0], [%1], 16;" :: "r"(dst), "l"(src));
}
#define CP_COMMIT() asm volatile("cp.async.commit_group;" ::: "memory")
#define CP_WAIT2()  asm volatile("cp.async.wait_group 2;" ::: "memory")
#define CP_WAIT1()  asm volatile("cp.async.wait_group 1;" ::: "memory")
#define CP_WAIT0()  asm volatile("cp.async.wait_group 0;" ::: "memory")

__device__ __forceinline__ void ldm4(uint32_t* r, uint32_t addr) {
    asm volatile("ldmatrix.sync.aligned.m8n8.x4.shared.b16 {%0,%1,%2,%3}, [%4];"
                 : "=r"(r[0]), "=r"(r[1]), "=r"(r[2]), "=r"(r[3]) : "r"(addr));
}
__device__ __forceinline__ void mma16816(float* d, const uint32_t* a, const uint32_t* b) {
    asm volatile(
        "mma.sync.aligned.m16n8k16.row.col.f32.bf16.bf16.f32 "
        "{%0,%1,%2,%3}, {%4,%5,%6,%7}, {%8,%9}, {%0,%1,%2,%3};"
        : "+f"(d[0]), "+f"(d[1]), "+f"(d[2]), "+f"(d[3])
        : "r"(a[0]), "r"(a[1]), "r"(a[2]), "r"(a[3]), "r"(b[0]), "r"(b[1]));
}
// Expand 2 spike bytes (u16, values 0/1) -> packed bf16x2 {1.0/0.0, 1.0/0.0}
__device__ __forceinline__ uint32_t spike2bf(uint32_t x) {
    uint32_t r;
    asm("prmt.b32 %0, %1, %2, 0x4140;" : "=r"(r) : "r"(x), "r"(0));
    return r * 0x3F80u;
}
__device__ __forceinline__ uint32_t prmt6420(uint32_t a, uint32_t b) {
    uint32_t r;
    asm("prmt.b32 %0, %1, %2, 0x6420;" : "=r"(r) : "r"(a), "r"(b));
    return r;
}

// Stage layout (bytes). W rows: 64B bf16 data + 16 pad = 80B.
// X rows (int8): 32B data + 16 pad = 48B.
constexpr uint32_t WH_OFF = 0;                  // 64 rows * 80  = 5120
constexpr uint32_t WL_OFF = 5120;               // 64 rows * 80  = 5120
constexpr uint32_t X0_OFF = 10240;              // 128 rows * 48 = 6144
constexpr uint32_t X1_OFF = 16384;              // 128 rows * 48 = 6144
constexpr uint32_t SSTG   = 22528;              // qkv stage size
constexpr uint32_t SSTG_P = 16384;              // p stage size (WH, WL, X)

// ---------------------------------------------------------------------------
// Kernel 0: split weights into bf16 hi + lo
// ---------------------------------------------------------------------------
__global__ __launch_bounds__(256) void split_w_kernel(const float* __restrict__ wq,
                                                      const float* __restrict__ wk,
                                                      const float* __restrict__ wv,
                                                      const float* __restrict__ wp) {
    int idx = blockIdx.x * 256 + threadIdx.x;
    int m = idx >> 16;
    int i = idx & 65535;
    const float* src = (m == 0) ? wq : (m == 1) ? wk : (m == 2) ? wv : wp;
    float w = src[i];
    __nv_bfloat16 hi = __float2bfloat16(w);
    float lo = w - __bfloat162float(hi);
    ((__nv_bfloat16*)g_whi4)[idx] = hi;
    ((__nv_bfloat16*)g_wlo4)[idx] = __float2bfloat16(lo);
}

// ---------------------------------------------------------------------------
// Kernel 1: input LIF -> xs (fp32 output) + g_xt8 (int8 transposed [n,c]).
// ---------------------------------------------------------------------------
__global__ __launch_bounds__(256) void lif_x_t_kernel(const float* __restrict__ x,
                                                      float* __restrict__ xs) {
    __shared__ __align__(16) uint16_t st[2][64][72];   // [t][c][n(+pad)], swizzled, 0/1
    int n0 = blockIdx.x * 64, c0 = blockIdx.y * 64, b = blockIdx.z;
    int tid = threadIdx.x;
    int tx = tid & 15, ty = tid >> 4;
#pragma unroll
    for (int cc = 0; cc < 4; ++cc) {
        int cl = cc * 16 + ty;
        int c = c0 + cl;
        size_t base0 = ((size_t)b * C_ + c) * N_ + n0 + tx * 4;
        size_t base1 = ((size_t)(B_ + b) * C_ + c) * N_ + n0 + tx * 4;
        float4 a0 = *(const float4*)&x[base0];
        float4 a1 = *(const float4*)&x[base1];
        float4 r0, r1;
        const float* p0 = (const float*)&a0;
        const float* p1 = (const float*)&a1;
        float* q0 = (float*)&r0;
        float* q1 = (float*)&r1;
        uint16_t h0[4], h1[4];
#pragma unroll
        for (int i = 0; i < 4; i++) {
            float v = p0[i] * 0.5f;
            float s0 = (v >= 1.0f) ? 1.0f : 0.0f;
            if (s0 != 0.0f) v = 0.0f;
            v = v + (p1[i] - v) * 0.5f;
            float s1 = (v >= 1.0f) ? 1.0f : 0.0f;
            q0[i] = s0;
            q1[i] = s1;
            h0[i] = (s0 != 0.0f) ? 1 : 0;
            h1[i] = (s1 != 0.0f) ? 1 : 0;
        }
        *(float4*)&xs[base0] = r0;
        *(float4*)&xs[base1] = r1;
        int col = (tx * 4) ^ (((cl >> 3) & 7) << 3);
        uint2 w0 = make_uint2((uint32_t)h0[0] | ((uint32_t)h0[1] << 16),
                              (uint32_t)h0[2] | ((uint32_t)h0[3] << 16));
        uint2 w1 = make_uint2((uint32_t)h1[0] | ((uint32_t)h1[1] << 16),
                              (uint32_t)h1[2] | ((uint32_t)h1[3] << 16));
        *(uint2*)&st[0][cl][col] = w0;
        *(uint2*)&st[1][cl][col] = w1;
    }
    __syncthreads();
    uint8_t* xt = (uint8_t*)g_xt8_4;
    // Each thread writes 2 uint4 (16 c-bytes each)
#pragma unroll
    for (int io = 0; io < 2; ++io) {
        int idx = tid * 2 + io;          // 0..511
        int t = idx >> 8;
        int rem = idx & 255;
        int nl = rem >> 2;
        int cg = rem & 3;                // 16-channel group
        uint32_t w32[4];
#pragma unroll
        for (int q = 0; q < 4; ++q) {
            int rbase = cg * 16 + q * 4;
            uint32_t v0 = st[t][rbase + 0][nl ^ ((((rbase + 0) >> 3) & 7) << 3)];
            uint32_t v1 = st[t][rbase + 1][nl ^ ((((rbase + 1) >> 3) & 7) << 3)];
            uint32_t v2 = st[t][rbase + 2][nl ^ ((((rbase + 2) >> 3) & 7) << 3)];
            uint32_t v3 = st[t][rbase + 3][nl ^ ((((rbase + 3) >> 3) & 7) << 3)];
            w32[q] = prmt6420(v0 | (v1 << 16), v2 | (v3 << 16));
        }
        *(uint4*)&xt[((size_t)(t * B_ + b) * N_ + n0 + nl) * C_ + c0 + cg * 16] =
            make_uint4(w32[0], w32[1], w32[2], w32[3]);
    }
}

// ---------------------------------------------------------------------------
// Kernel 2: HMMA GEMM for q/k/v + BN + LIF; fp32 spike outputs + bit-packed
// spikes. B operand built from int8 spikes via LDS.U16 + PRMT (no ldmatrix).
// 4-stage cp.async pipeline, one __syncthreads per K-chunk.
// MODE 0: pack along channel (q). MODE 1: pack along n (k, v).
// ---------------------------------------------------------------------------
template <int MODE>
__global__ __launch_bounds__(256) void hmma_qkv(
    int widx, float* __restrict__ outp,
    const float* __restrict__ gamma, const float* __restrict__ beta,
    const float* __restrict__ mean, const float* __restrict__ var) {
    extern __shared__ __align__(16) char smem[];
    uint32_t sb = smem_u32(smem);
    const int tid = threadIdx.x;
    const int lane = tid & 31;
    const int wid = tid >> 5;
    const int wo = wid >> 2;
    const int wn = wid & 3;
    const int n0 = blockIdx.x * 128;
    const int o0 = blockIdx.y * 64;
    const int b  = blockIdx.z;

    const __nv_bfloat16* wh = (const __nv_bfloat16*)g_whi4 + widx * 65536 + o0 * C_;
    const __nv_bfloat16* wl = (const __nv_bfloat16*)g_wlo4 + widx * 65536 + o0 * C_;
    const uint8_t* xt = (const uint8_t*)g_xt8_4;
    const uint8_t* x0g = xt + ((size_t)b * N_ + n0) * C_;
    const uint8_t* x1g = xt + ((size_t)(B_ + b) * N_ + n0) * C_;

    float d[2][4][2][4];
#pragma unroll
    for (int a = 0; a < 2; a++)
#pragma unroll
        for (int c = 0; c < 4; c++)
#pragma unroll
            for (int t = 0; t < 2; t++)
#pragma unroll
                for (int j = 0; j < 4; j++) d[a][c][t][j] = 0.f;

    auto load_chunk = [&](int c0, int stg) {
        uint32_t s0 = sb + (uint32_t)stg * SSTG;
        cp16(s0 + WH_OFF + (tid >> 2) * 80 + (tid & 3) * 16,
             wh + (size_t)(tid >> 2) * C_ + c0 + (tid & 3) * 8);
        cp16(s0 + WL_OFF + (tid >> 2) * 80 + (tid & 3) * 16,
             wl + (size_t)(tid >> 2) * C_ + c0 + (tid & 3) * 8);
        cp16(s0 + X0_OFF + (tid >> 1) * 48 + (tid & 1) * 16,
             x0g + (size_t)(tid >> 1) * C_ + c0 + (tid & 1) * 16);
        cp16(s0 + X1_OFF + (tid >> 1) * 48 + (tid & 1) * 16,
             x1g + (size_t)(tid >> 1) * C_ + c0 + (tid & 1) * 16);
    };

    // W chunks are 32 bf16 columns (64B); X chunks are 32 int8 columns (32B).
    // W c0 arg is in bf16 elements; X c0 arg in bytes — both equal 32*ch.
    load_chunk(0, 0);  CP_COMMIT();
    load_chunk(32, 1); CP_COMMIT();
    load_chunk(64, 2); CP_COMMIT();

    const int arow = (lane & 7) + ((lane >> 3) & 1) * 8;   // A row add
    const int acol = ((lane >> 4) & 1) * 16;               // A k byte add
    const int brows = lane >> 2;                           // B: n row within 8
    const int bk = 2 * (lane & 3);                         // B: k byte offset

#pragma unroll
    for (int ch = 0; ch < 8; ++ch) {
        if (ch < 6) { CP_WAIT2(); } else if (ch == 6) { CP_WAIT1(); } else { CP_WAIT0(); }
        __syncthreads();
        if (ch + 3 < 8) {
            load_chunk((ch + 3) * 32, (ch + 3) & 3);
            CP_COMMIT();
        }
        uint32_t stgoff = (uint32_t)(ch & 3) * SSTG;
        uint32_t aW = sb + stgoff + WH_OFF + (wo * 32) * 80;
        int xoff = (int)stgoff + (int)X0_OFF + (wn * 32 + brows) * 48 + bk;
#pragma unroll
        for (int k16 = 0; k16 < 2; ++k16) {
            int kb = k16 * 32;          // W byte offset (bf16)
            int kbx = k16 * 16;         // X byte offset (int8)
            uint32_t ah[2][4], al[2][4];
#pragma unroll
            for (int ot = 0; ot < 2; ++ot) {
                uint32_t ad = aW + (uint32_t)(ot * 16 + arow) * 80 + kb + acol;
                ldm4(ah[ot], ad);
                ldm4(al[ot], ad + (WL_OFF - WH_OFF));
            }
            uint32_t bf[2][4][2];
#pragma unroll
            for (int t = 0; t < 2; ++t) {
#pragma unroll
                for (int nt = 0; nt < 4; ++nt) {
                    int off = xoff + t * (int)(X1_OFF - X0_OFF) + nt * 8 * 48 + kbx;
                    uint32_t xlo = *(const uint16_t*)(smem + off);
                    uint32_t xhi = *(const uint16_t*)(smem + off + 8);
                    bf[t][nt][0] = spike2bf(xlo);
                    bf[t][nt][1] = spike2bf(xhi);
                }
            }
#pragma unroll
            for (int t = 0; t < 2; ++t)
#pragma unroll
                for (int ot = 0; ot < 2; ++ot)
#pragma unroll
                    for (int nt = 0; nt < 4; ++nt) {
                        mma16816(d[ot][nt][t], ah[ot], bf[t][nt]);
                        mma16816(d[ot][nt][t], al[ot], bf[t][nt]);
                    }
        }
    }

    // Epilogue: BN + LIF, fp32 spike stores + bit packing
    const int la = lane & 3;
    const int g  = lane >> 2;
    const int obase = o0 + wo * 32 + g;
    const int nbase = n0 + wn * 32 + 2 * la;

    uint32_t pk[2][2][2];
    uint32_t pc[2][4][2];
#pragma unroll
    for (int t = 0; t < 2; ++t) {
#pragma unroll
        for (int i = 0; i < 2; ++i)
#pragma unroll
            for (int j = 0; j < 2; ++j) pk[t][i][j] = 0u;
#pragma unroll
        for (int i = 0; i < 4; ++i)
#pragma unroll
            for (int j = 0; j < 2; ++j) pc[t][i][j] = 0u;
    }

#pragma unroll
    for (int ot = 0; ot < 2; ++ot) {
#pragma unroll
        for (int rr = 0; rr < 2; ++rr) {
            int o = obase + ot * 16 + rr * 8;
            float gm = __ldg(&gamma[o]);
            float sq = sqrtf(__ldg(&var[o]) + 1e-5f);
            float inv = gm / sq;
            float sh  = __ldg(&beta[o]) - __ldg(&mean[o]) * gm / sq;
            size_t ro0 = ((size_t)b * C_ + o) * N_;
            size_t ro1 = ((size_t)(B_ + b) * C_ + o) * N_;
#pragma unroll
            for (int nt = 0; nt < 4; ++nt) {
                int n = nbase + nt * 8;
                float s0v[2], s1v[2];
#pragma unroll
                for (int cc = 0; cc < 2; ++cc) {
                    float y0 = d[ot][nt][0][rr * 2 + cc] * inv + sh;
                    float y1 = d[ot][nt][1][rr * 2 + cc] * inv + sh;
                    float v = y0 * 0.5f;
                    float sp0 = (v >= 1.0f) ? 1.0f : 0.0f;
                    if (sp0 != 0.0f) v = 0.0f;
                    v = v + (y1 - v) * 0.5f;
                    float sp1 = (v >= 1.0f) ? 1.0f : 0.0f;
                    s0v[cc] = sp0;
                    s1v[cc] = sp1;
                    if (MODE == 0) {
                        uint32_t bit = 1u << (g + rr * 8 + ot * 16);
                        if (sp0 != 0.0f) pc[0][nt][cc] |= bit;
                        if (sp1 != 0.0f) pc[1][nt][cc] |= bit;
                    } else {
                        uint32_t bit = 1u << (nt * 8 + la * 2 + cc);
                        if (sp0 != 0.0f) pk[0][ot][rr] |= bit;
                        if (sp1 != 0.0f) pk[1][ot][rr] |= bit;
                    }
                }
                *(float2*)&outp[ro0 + n] = make_float2(s0v[0], s0v[1]);
                *(float2*)&outp[ro1 + n] = make_float2(s1v[0], s1v[1]);
            }
        }
    }

    if (MODE == 0) {
        const int hword = (o0 + wo * 32) >> 5;
#pragma unroll
        for (int t = 0; t < 2; ++t)
#pragma unroll
            for (int nt = 0; nt < 4; ++nt)
#pragma unroll
                for (int cc = 0; cc < 2; ++cc) {
                    uint32_t w = pc[t][nt][cc];
                    w |= __shfl_xor_sync(0xffffffffu, w, 4);
                    w |= __shfl_xor_sync(0xffffffffu, w, 8);
                    w |= __shfl_xor_sync(0xffffffffu, w, 16);
                    if (g == 0) {
                        int n = nbase + nt * 8 + cc;
                        g_qpk[((size_t)(t * B_ + b) * N_ + n) * 8 + hword] = w;
                    }
                }
    } else {
        uint32_t* pko = (widx == 1) ? g_kpk : g_vpk;
        const int nw = (n0 + wn * 32) >> 5;
#pragma unroll
        for (int t = 0; t < 2; ++t)
#pragma unroll
            for (int ot = 0; ot < 2; ++ot)
#pragma unroll
                for (int rr = 0; rr < 2; ++rr) {
                    uint32_t w = pk[t][ot][rr];
                    w |= __shfl_xor_sync(0xffffffffu, w, 1);
                    w |= __shfl_xor_sync(0xffffffffu, w, 2);
                    if (la == 0) {
                        int o = obase + ot * 16 + rr * 8;
                        pko[((size_t)(t * B_ + b) * C_ + o) * 128 + nw] = w;
                    }
                }
    }
}

// ---------------------------------------------------------------------------
// Kernel 3: kv via popcount over packed bits
// ---------------------------------------------------------------------------
__global__ __launch_bounds__(256) void kv_pk_kernel() {
    int h = blockIdx.x, b = blockIdx.y, t = blockIdx.z;
    int tb = t * B_ + b;
    __shared__ uint32_t ks[32 * 129];
    __shared__ uint32_t vs[32 * 129];
    int tid = threadIdx.x;
    const uint32_t* kp = g_kpk + ((size_t)tb * C_ + h * D_) * 128;
    const uint32_t* vp = g_vpk + ((size_t)tb * C_ + h * D_) * 128;
    for (int i = tid; i < 4096; i += 256) {
        int dd = i >> 7, w = i & 127;
        ks[dd * 129 + w] = kp[i];
        vs[dd * 129 + w] = vp[i];
    }
    __syncthreads();
    float* kvout = g_kv + ((size_t)tb * NH_ + h) * (D_ * D_);
    for (int p = tid; p < 1024; p += 256) {
        int dd = p >> 5, e = p & 31;
        const uint32_t* kd = ks + dd * 129;
        const uint32_t* ve = vs + e * 129;
        int acc = 0;
#pragma unroll 8
        for (int w = 0; w < 128; ++w) acc += __popc(kd[w] & ve[w]);
        kvout[p] = (float)acc;
    }
}

// ---------------------------------------------------------------------------
// Kernel 4: attn via masked row-sum, LIF(0.5) -> g_st8 (int8 [n,c])
// ---------------------------------------------------------------------------
__global__ __launch_bounds__(256) void attn_pk_kernel() {
    __shared__ float kvs[2][32][33];
    int n0 = blockIdx.x * 128;
    int h = blockIdx.y;
    int b = blockIdx.z;
    int tid = threadIdx.x;

    for (int l = tid; l < 2048; l += 256) {
        int t = l >> 10;
        int r = l & 1023;
        kvs[t][r >> 5][r & 31] = g_kv[((size_t)(t * B_ + b) * NH_ + h) * 1024 + r];
    }
    __syncthreads();

    int nl = tid >> 1;
    int eh = (tid & 1) * 16;
    int nn = n0 + nl;
    uint32_t qw0 = g_qpk[((size_t)b * N_ + nn) * 8 + h];
    uint32_t qw1 = g_qpk[((size_t)(B_ + b) * N_ + nn) * 8 + h];

    float a0[16], a1[16];
#pragma unroll
    for (int j = 0; j < 16; ++j) { a0[j] = 0.f; a1[j] = 0.f; }
#pragma unroll 4
    for (int dd = 0; dd < 32; ++dd) {
        if ((qw0 >> dd) & 1) {
#pragma unroll
            for (int j = 0; j < 16; ++j) a0[j] += kvs[0][dd][eh + j];
        }
        if ((qw1 >> dd) & 1) {
#pragma unroll
            for (int j = 0; j < 16; ++j) a1[j] += kvs[1][dd][eh + j];
        }
    }

    uint32_t w0[4] = {0, 0, 0, 0}, w1[4] = {0, 0, 0, 0};
#pragma unroll
    for (int j = 0; j < 16; ++j) {
        float y0 = a0[j] * 0.125f;
        float y1 = a1[j] * 0.125f;
        float v = y0 * 0.5f;
        float t0 = (v >= 0.5f) ? 1.0f : 0.0f;
        if (t0 != 0.0f) v = 0.0f;
        v = v + (y1 - v) * 0.5f;
        float t1 = (v >= 0.5f) ? 1.0f : 0.0f;
        if (t0 != 0.0f) w0[j >> 2] |= 1u << ((j & 3) * 8);
        if (t1 != 0.0f) w1[j >> 2] |= 1u << ((j & 3) * 8);
    }
    uint8_t* stt = (uint8_t*)g_st8_4;
    size_t b0 = ((size_t)b * N_ + nn) * C_ + h * D_ + eh;
    size_t b1 = ((size_t)(B_ + b) * N_ + nn) * C_ + h * D_ + eh;
    *(uint4*)&stt[b0] = make_uint4(w0[0], w0[1], w0[2], w0[3]);
    *(uint4*)&stt[b1] = make_uint4(w1[0], w1[1], w1[2], w1[3]);
}

// ---------------------------------------------------------------------------
// Kernel 5: HMMA projection GEMM: out = BN(Wp @ s + bp). 4-stage pipeline,
// B operand from int8 S spikes.
// ---------------------------------------------------------------------------
__global__ __launch_bounds__(256) void hmma_p(
    float* __restrict__ outp, const float* __restrict__ bp,
    const float* __restrict__ gamma, const float* __restrict__ beta,
    const float* __restrict__ mean, const float* __restrict__ var) {
    extern __shared__ __align__(16) char smem[];
    uint32_t sb = smem_u32(smem);
    const int tid = threadIdx.x;
    const int lane = tid & 31;
    const int wid = tid >> 5;
    const int wo = wid >> 2;
    const int wn = wid & 3;
    const int n0 = blockIdx.x * 128;
    const int o0 = blockIdx.y * 64;
    const int z  = blockIdx.z;

    const __nv_bfloat16* wh = (const __nv_bfloat16*)g_whi4 + 3 * 65536 + o0 * C_;
    const __nv_bfloat16* wl = (const __nv_bfloat16*)g_wlo4 + 3 * 65536 + o0 * C_;
    const uint8_t* xg = (const uint8_t*)g_st8_4 + ((size_t)z * N_ + n0) * C_;

    float d[2][4][4];
#pragma unroll
    for (int a = 0; a < 2; a++)
#pragma unroll
        for (int c = 0; c < 4; c++)
#pragma unroll
            for (int j = 0; j < 4; j++) d[a][c][j] = 0.f;

    auto load_chunk = [&](int c0, int stg) {
        uint32_t s0 = sb + (uint32_t)stg * SSTG_P;
        cp16(s0 + WH_OFF + (tid >> 2) * 80 + (tid & 3) * 16,
             wh + (size_t)(tid >> 2) * C_ + c0 + (tid & 3) * 8);
        cp16(s0 + WL_OFF + (tid >> 2) * 80 + (tid & 3) * 16,
             wl + (size_t)(tid >> 2) * C_ + c0 + (tid & 3) * 8);
        cp16(s0 + X0_OFF + (tid >> 1) * 48 + (tid & 1) * 16,
             xg + (size_t)(tid >> 1) * C_ + c0 + (tid & 1) * 16);
    };

    load_chunk(0, 0);  CP_COMMIT();
    load_chunk(32, 1); CP_COMMIT();
    load_chunk(64, 2); CP_COMMIT();

    const int arow = (lane & 7) + ((lane >> 3) & 1) * 8;
    const int acol = ((lane >> 4) & 1) * 16;
    const int brows = lane >> 2;
    const int bk = 2 * (lane & 3);

#pragma unroll
    for (int ch = 0; ch < 8; ++ch) {
        if (ch < 6) { CP_WAIT2(); } else if (ch == 6) { CP_WAIT1(); } else { CP_WAIT0(); }
        __syncthreads();
        if (ch + 3 < 8) {
            load_chunk((ch + 3) * 32, (ch + 3) & 3);
            CP_COMMIT();
        }
        uint32_t stgoff = (uint32_t)(ch & 3) * SSTG_P;
        uint32_t aW = sb + stgoff + WH_OFF + (wo * 32) * 80;
        int xoff = (int)stgoff + (int)X0_OFF + (wn * 32 + brows) * 48 + bk;
#pragma unroll
        for (int k16 = 0; k16 < 2; ++k16) {
            int kb = k16 * 32;
            int kbx = k16 * 16;
            uint32_t ah[2][4], al[2][4];
#pragma unroll
            for (int ot = 0; ot < 2; ++ot) {
                uint32_t ad = aW + (uint32_t)(ot * 16 + arow) * 80 + kb + acol;
                ldm4(ah[ot], ad);
                ldm4(al[ot], ad + (WL_OFF - WH_OFF));
            }
            uint32_t bf[4][2];
#pragma unroll
            for (int nt = 0; nt < 4; ++nt) {
                int off = xoff + nt * 8 * 48 + kbx;
                uint32_t xlo = *(const uint16_t*)(smem + off);
                uint32_t xhi = *(const uint16_t*)(smem + off + 8);
                bf[nt][0] = spike2bf(xlo);
                bf[nt][1] = spike2bf(xhi);
            }
#pragma unroll
            for (int ot = 0; ot < 2; ++ot)
#pragma unroll
                for (int nt = 0; nt < 4; ++nt) {
                    mma16816(d[ot][nt], ah[ot], bf[nt]);
                    mma16816(d[ot][nt], al[ot], bf[nt]);
                }
        }
    }

    const int obase = o0 + wo * 32 + (lane >> 2);
    const int nbase = n0 + wn * 32 + 2 * (lane & 3);
#pragma unroll
    for (int ot = 0; ot < 2; ++ot) {
#pragma unroll
        for (int rr = 0; rr < 2; ++rr) {
            int o = obase + ot * 16 + rr * 8;
            float g  = __ldg(&gamma[o]);
            float sq = sqrtf(__ldg(&var[o]) + 1e-5f);
            float inv = g / sq;
            float sh  = __ldg(&beta[o]) - __ldg(&mean[o]) * g / sq;
            float bb  = __ldg(&bp[o]);
            size_t ro = ((size_t)z * C_ + o) * N_;
#pragma unroll
            for (int nt = 0; nt < 4; ++nt) {
                int n = nbase + nt * 8;
                float y0 = (d[ot][nt][rr * 2 + 0] + bb) * inv + sh;
                float y1 = (d[ot][nt][rr * 2 + 1] + bb) * inv + sh;
                *(float2*)&outp[ro + n] = make_float2(y0, y1);
            }
        }
    }
}

// ---------------------------------------------------------------------------
extern "C" void kernel_launch(void* const* d_in, const int* in_sizes, int n_in,
                              void* d_out, int out_size) {
    const float* x  = (const float*)d_in[0];
    const float* wq = (const float*)d_in[1];
    const float* wk = (const float*)d_in[2];
    const float* wv = (const float*)d_in[3];
    const float* wp = (const float*)d_in[4];
    const float* bp = (const float*)d_in[5];
    const float* qg = (const float*)d_in[6];
    const float* qb = (const float*)d_in[7];
    const float* qm = (const float*)d_in[8];
    const float* qv = (const float*)d_in[9];
    const float* kg = (const float*)d_in[10];
    const float* kb = (const float*)d_in[11];
    const float* km = (const float*)d_in[12];
    const float* kv_ = (const float*)d_in[13];
    const float* vg = (const float*)d_in[14];
    const float* vb = (const float*)d_in[15];
    const float* vm = (const float*)d_in[16];
    const float* vv = (const float*)d_in[17];
    const float* pg = (const float*)d_in[18];
    const float* pb = (const float*)d_in[19];
    const float* pm = (const float*)d_in[20];
    const float* pv = (const float*)d_in[21];

    float* out = (float*)d_out;
    float* xs = out + (size_t)SZ;
    float* qo = out + 2 * (size_t)SZ;
    float* ko = out + 3 * (size_t)SZ;
    float* vo = out + 4 * (size_t)SZ;

    cudaFuncSetAttribute(hmma_qkv<0>, cudaFuncAttributeMaxDynamicSharedMemorySize, 4 * SSTG);
    cudaFuncSetAttribute(hmma_qkv<1>, cudaFuncAttributeMaxDynamicSharedMemorySize, 4 * SSTG);
    cudaFuncSetAttribute(hmma_p, cudaFuncAttributeMaxDynamicSharedMemorySize, 4 * SSTG_P);

    // 0) weight split
    split_w_kernel<<<1024, 256>>>(wq, wk, wv, wp);

    // 1) input LIF -> xs (fp32) + transposed int8 activations
    lif_x_t_kernel<<<dim3(N_ / 64, C_ / 64, B_), 256>>>(x, xs);

    // 2) q/k/v HMMA GEMM + BN + LIF (+ bit packing)
    dim3 gg(N_ / 128, C_ / 64, B_);
    hmma_qkv<0><<<gg, 256, 4 * SSTG>>>(0, qo, qg, qb, qm, qv);
    hmma_qkv<1><<<gg, 256, 4 * SSTG>>>(1, ko, kg, kb, km, kv_);
    hmma_qkv<1><<<gg, 256, 4 * SSTG>>>(2, vo, vg, vb, vm, vv);

    // 3) kv via popcount
    kv_pk_kernel<<<dim3(NH_, B_, T_), 256>>>();

    // 4) attn via masked row-sum + LIF(0.5) -> int8 spikes
    attn_pk_kernel<<<dim3(N_ / 128, NH_, B_), 256>>>();

    // 5) projection HMMA GEMM + bias + BN -> out
    hmma_p<<<dim3(N_ / 128, C_ / 64, T_ * B_), 256, 4 * SSTG_P>>>(
        out, bp, pg, pb, pm, pv);
}

// round 17
// speedup vs baseline: 1.1072x; 1.1072x over previous
#include <cuda_runtime.h>
#include <cuda_bf16.h>
#include <math.h>
#include <stdint.h>

// Problem constants
#define T_  2
#define B_  16
#define C_  256
#define N_  4096
#define NH_ 8
#define D_  32

constexpr int TSTR = B_ * C_ * N_;
constexpr int SZ   = T_ * TSTR;

// ---------------------------------------------------------------------------
// Scratch (device globals)
// ---------------------------------------------------------------------------
__device__ uint4 g_xt4[SZ / 8];              // bf16 xs transposed [t,b][n][c]
__device__ uint4 g_st4[SZ / 8];              // bf16 attn spikes transposed [t,b][n][c]
__device__ uint4 g_whi4[4 * 65536 / 8];      // bf16 W_hi {q,k,v,p}
__device__ uint4 g_wlo4[4 * 65536 / 8];      // bf16 W_lo
__device__ float g_kv[T_ * B_ * NH_ * D_ * D_];
__device__ uint32_t g_qpk[32 * N_ * 8];      // q bits packed along channel
__device__ uint32_t g_kpk[32 * C_ * 128];    // k bits packed along n
__device__ uint32_t g_vpk[32 * C_ * 128];    // v bits packed along n

// ---------------------------------------------------------------------------
// PTX helpers (arch-agnostic)
// ---------------------------------------------------------------------------
__device__ __forceinline__ uint32_t smem_u32(const void* p) {
    uint32_t a;
    asm("{ .reg .u64 t; cvta.to.shared.u64 t, %1; cvt.u32.u64 %0, t; }"
        : "=r"(a) : "l"(p));
    return a;
}
__device__ __forceinline__ void cp16(uint32_t dst, const void* src) {
    asm volatile("cp.async.ca.shared.global [%0], [%1], 16;" :: "r"(dst), "l"(src));
}
#define CP_COMMIT() asm volatile("cp.async.commit_group;" ::: "memory")
#define CP_WAIT1()  asm volatile("cp.async.wait_group 1;" ::: "memory")
#define CP_WAIT0()  asm volatile("cp.async.wait_group 0;" ::: "memory")

__device__ __forceinline__ void ldm4(uint32_t* r, uint32_t addr) {
    asm volatile("ldmatrix.sync.aligned.m8n8.x4.shared.b16 {%0,%1,%2,%3}, [%4];"
                 : "=r"(r[0]), "=r"(r[1]), "=r"(r[2]), "=r"(r[3]) : "r"(addr));
}
__device__ __forceinline__ void mma16816(float* d, const uint32_t* a, const uint32_t* b) {
    asm volatile(
        "mma.sync.aligned.m16n8k16.row.col.f32.bf16.bf16.f32 "
        "{%0,%1,%2,%3}, {%4,%5,%6,%7}, {%8,%9}, {%0,%1,%2,%3};"
        : "+f"(d[0]), "+f"(d[1]), "+f"(d[2]), "+f"(d[3])
        : "r"(a[0]), "r"(a[1]), "r"(a[2]), "r"(a[3]), "r"(b[0]), "r"(b[1]));
}

// qkv stage layout (hi-only W): W rows 80B, X rows 80B
constexpr uint32_t QW_OFF  = 0;        // 64 rows * 80 = 5120
constexpr uint32_t QX0_OFF = 5120;     // 128 rows * 80 = 10240
constexpr uint32_t QX1_OFF = 15360;    // 128 rows * 80 = 10240
constexpr uint32_t SSTG_Q  = 25600;

// p stage layout (hi+lo W)
constexpr uint32_t WH_OFF = 0;
constexpr uint32_t WL_OFF = 5120;
constexpr uint32_t X0_OFF = 10240;
constexpr uint32_t SSTG_P = 20480;

// ---------------------------------------------------------------------------
// Kernel 0: split weights into bf16 hi + lo
// ---------------------------------------------------------------------------
__global__ __launch_bounds__(256) void split_w_kernel(const float* __restrict__ wq,
                                                      const float* __restrict__ wk,
                                                      const float* __restrict__ wv,
                                                      const float* __restrict__ wp) {
    int idx = blockIdx.x * 256 + threadIdx.x;
    int m = idx >> 16;
    int i = idx & 65535;
    const float* src = (m == 0) ? wq : (m == 1) ? wk : (m == 2) ? wv : wp;
    float w = src[i];
    __nv_bfloat16 hi = __float2bfloat16(w);
    float lo = w - __bfloat162float(hi);
    ((__nv_bfloat16*)g_whi4)[idx] = hi;
    ((__nv_bfloat16*)g_wlo4)[idx] = __float2bfloat16(lo);
}

// ---------------------------------------------------------------------------
// Kernel 1: input LIF -> xs (fp32 output) + g_xt (bf16 transposed [n,c]).
// ---------------------------------------------------------------------------
__global__ __launch_bounds__(256) void lif_x_t_kernel(const float* __restrict__ x,
                                                      float* __restrict__ xs) {
    __shared__ __align__(16) uint16_t st[2][64][72];   // [t][c][n(+pad)], swizzled
    int n0 = blockIdx.x * 64, c0 = blockIdx.y * 64, b = blockIdx.z;
    int tid = threadIdx.x;
    int tx = tid & 15, ty = tid >> 4;
#pragma unroll
    for (int cc = 0; cc < 4; ++cc) {
        int cl = cc * 16 + ty;
        int c = c0 + cl;
        size_t base0 = ((size_t)b * C_ + c) * N_ + n0 + tx * 4;
        size_t base1 = ((size_t)(B_ + b) * C_ + c) * N_ + n0 + tx * 4;
        float4 a0 = *(const float4*)&x[base0];
        float4 a1 = *(const float4*)&x[base1];
        float4 r0, r1;
        const float* p0 = (const float*)&a0;
        const float* p1 = (const float*)&a1;
        float* q0 = (float*)&r0;
        float* q1 = (float*)&r1;
        uint16_t h0[4], h1[4];
#pragma unroll
        for (int i = 0; i < 4; i++) {
            float v = p0[i] * 0.5f;
            float s0 = (v >= 1.0f) ? 1.0f : 0.0f;
            if (s0 != 0.0f) v = 0.0f;
            v = v + (p1[i] - v) * 0.5f;
            float s1 = (v >= 1.0f) ? 1.0f : 0.0f;
            q0[i] = s0;
            q1[i] = s1;
            h0[i] = (s0 != 0.0f) ? 0x3F80 : 0;   // bf16 1.0 / 0.0
            h1[i] = (s1 != 0.0f) ? 0x3F80 : 0;
        }
        *(float4*)&xs[base0] = r0;
        *(float4*)&xs[base1] = r1;
        int col = (tx * 4) ^ (((cl >> 3) & 7) << 3);
        uint2 w0 = make_uint2((uint32_t)h0[0] | ((uint32_t)h0[1] << 16),
                              (uint32_t)h0[2] | ((uint32_t)h0[3] << 16));
        uint2 w1 = make_uint2((uint32_t)h1[0] | ((uint32_t)h1[1] << 16),
                              (uint32_t)h1[2] | ((uint32_t)h1[3] << 16));
        *(uint2*)&st[0][cl][col] = w0;
        *(uint2*)&st[1][cl][col] = w1;
    }
    __syncthreads();
    __nv_bfloat16* xt = (__nv_bfloat16*)g_xt4;
#pragma unroll
    for (int it = 0; it < 4; ++it) {
        int u = tid + it * 256;            // 0..1023
        int t = u >> 9;
        int r = u & 511;
        int nl = r >> 3;
        int c8 = r & 7;
        int col = nl ^ (c8 << 3);
        uint32_t w[4];
#pragma unroll
        for (int jp = 0; jp < 4; ++jp) {
            uint32_t lo = st[t][c8 * 8 + jp * 2][col];
            uint32_t hi = st[t][c8 * 8 + jp * 2 + 1][col];
            w[jp] = lo | (hi << 16);
        }
        *(uint4*)&xt[((size_t)(t * B_ + b) * N_ + n0 + nl) * C_ + c0 + c8 * 8] =
            make_uint4(w[0], w[1], w[2], w[3]);
    }
}

// ---------------------------------------------------------------------------
// Kernel 2: HMMA GEMM for q/k/v (HI-ONLY) + BN + LIF + threshold-margin
// exact correction from fp32 W. fp32 spike outputs + bit-packed spikes.
// MODE 0: pack along channel (q). MODE 1: pack along n (k, v).
// ---------------------------------------------------------------------------
template <int MODE>
__global__ __launch_bounds__(256) void hmma_qkv(
    int widx, const float* __restrict__ wfull, float* __restrict__ outp,
    const float* __restrict__ gamma, const float* __restrict__ beta,
    const float* __restrict__ mean, const float* __restrict__ var) {
    extern __shared__ __align__(16) char smem[];
    uint32_t sb = smem_u32(smem);
    const int tid = threadIdx.x;
    const int lane = tid & 31;
    const int wid = tid >> 5;
    const int wo = wid >> 2;
    const int wn = wid & 3;
    const int n0 = blockIdx.x * 128;
    const int o0 = blockIdx.y * 64;
    const int b  = blockIdx.z;

    const __nv_bfloat16* wh = (const __nv_bfloat16*)g_whi4 + widx * 65536 + o0 * C_;
    const __nv_bfloat16* xt = (const __nv_bfloat16*)g_xt4;
    const __nv_bfloat16* x0g = xt + ((size_t)b * N_ + n0) * C_;
    const __nv_bfloat16* x1g = xt + ((size_t)(B_ + b) * N_ + n0) * C_;

    float d[2][4][2][4];
#pragma unroll
    for (int a = 0; a < 2; a++)
#pragma unroll
        for (int c = 0; c < 4; c++)
#pragma unroll
            for (int t = 0; t < 2; t++)
#pragma unroll
                for (int j = 0; j < 4; j++) d[a][c][t][j] = 0.f;

    const int lr = tid >> 2;
    const int lj = tid & 3;
    auto load_chunk = [&](int c0, int stg) {
        uint32_t s0 = sb + (uint32_t)stg * SSTG_Q;
        cp16(s0 + QW_OFF + lr * 80 + lj * 16, wh + (size_t)lr * C_ + c0 + lj * 8);
        cp16(s0 + QX0_OFF + lr * 80 + lj * 16, x0g + (size_t)lr * C_ + c0 + lj * 8);
        cp16(s0 + QX0_OFF + (64 + lr) * 80 + lj * 16, x0g + (size_t)(64 + lr) * C_ + c0 + lj * 8);
        cp16(s0 + QX1_OFF + lr * 80 + lj * 16, x1g + (size_t)lr * C_ + c0 + lj * 8);
        cp16(s0 + QX1_OFF + (64 + lr) * 80 + lj * 16, x1g + (size_t)(64 + lr) * C_ + c0 + lj * 8);
    };

    load_chunk(0, 0);
    CP_COMMIT();
    load_chunk(32, 1);
    CP_COMMIT();

    const int arow = (lane & 7) + ((lane >> 3) & 1) * 8;
    const int acol = ((lane >> 4) & 1) * 16;
    const int brow = (lane & 7) + ((lane >> 4) & 1) * 8;
    const int bcol = ((lane >> 3) & 1) * 16;

#pragma unroll
    for (int ch = 0; ch < 8; ++ch) {
        if (ch < 7) { CP_WAIT1(); } else { CP_WAIT0(); }
        __syncthreads();
        if (ch + 2 < 8) {
            load_chunk((ch + 2) * 32, (ch + 2) % 3);
            CP_COMMIT();
        }
        uint32_t s0 = sb + (uint32_t)(ch % 3) * SSTG_Q;
        uint32_t aW = s0 + QW_OFF + (wo * 32) * 80;
        uint32_t aX = s0 + QX0_OFF + (wn * 32) * 80;
#pragma unroll
        for (int k16 = 0; k16 < 2; ++k16) {
            int kb = k16 * 32;
            uint32_t ah[2][4];
#pragma unroll
            for (int ot = 0; ot < 2; ++ot) {
                uint32_t ad = aW + (uint32_t)(ot * 16 + arow) * 80 + kb + acol;
                ldm4(ah[ot], ad);
            }
            uint32_t bf[2][4][2];
#pragma unroll
            for (int t = 0; t < 2; ++t) {
                uint32_t bbase = aX + (uint32_t)t * (QX1_OFF - QX0_OFF);
#pragma unroll
                for (int ns = 0; ns < 2; ++ns) {
                    uint32_t r[4];
                    ldm4(r, bbase + (uint32_t)(ns * 16 + brow) * 80 + kb + bcol);
                    bf[t][ns * 2][0] = r[0];
                    bf[t][ns * 2][1] = r[1];
                    bf[t][ns * 2 + 1][0] = r[2];
                    bf[t][ns * 2 + 1][1] = r[3];
                }
            }
#pragma unroll
            for (int t = 0; t < 2; ++t)
#pragma unroll
                for (int ot = 0; ot < 2; ++ot)
#pragma unroll
                    for (int nt = 0; nt < 4; ++nt)
                        mma16816(d[ot][nt][t], ah[ot], bf[t][nt]);
        }
    }

    // Epilogue: BN + LIF with margin-flagged exact correction, stores + packing
    const int la = lane & 3;
    const int g  = lane >> 2;
    const int obase = o0 + wo * 32 + g;
    const int nbase = n0 + wn * 32 + 2 * la;

    uint32_t pk[2][2][2];
    uint32_t pc[2][4][2];
#pragma unroll
    for (int t = 0; t < 2; ++t) {
#pragma unroll
        for (int i = 0; i < 2; ++i)
#pragma unroll
            for (int j = 0; j < 2; ++j) pk[t][i][j] = 0u;
#pragma unroll
        for (int i = 0; i < 4; ++i)
#pragma unroll
            for (int j = 0; j < 2; ++j) pc[t][i][j] = 0u;
    }

#pragma unroll
    for (int ot = 0; ot < 2; ++ot) {
#pragma unroll
        for (int rr = 0; rr < 2; ++rr) {
            int o = obase + ot * 16 + rr * 8;
            float gm = __ldg(&gamma[o]);
            float sq = sqrtf(__ldg(&var[o]) + 1e-5f);
            float inv = gm / sq;
            float sh  = __ldg(&beta[o]) - __ldg(&mean[o]) * gm / sq;
            float mg  = 0.01f * fabsf(inv);   // margin >> max |lo-sum| * inv
            const float* wrow = wfull + (size_t)o * C_;
            size_t ro0 = ((size_t)b * C_ + o) * N_;
            size_t ro1 = ((size_t)(B_ + b) * C_ + o) * N_;
#pragma unroll
            for (int nt = 0; nt < 4; ++nt) {
                int n = nbase + nt * 8;
                float s0v[2], s1v[2];
#pragma unroll
                for (int cc = 0; cc < 2; ++cc) {
                    float y0 = d[ot][nt][0][rr * 2 + cc] * inv + sh;
                    float y1 = d[ot][nt][1][rr * 2 + cc] * inv + sh;
                    float v0 = y0 * 0.5f;
                    float sp0 = (v0 >= 1.0f) ? 1.0f : 0.0f;
                    float vv = (sp0 != 0.0f) ? 0.0f : v0;
                    float v1 = vv + (y1 - vv) * 0.5f;
                    bool flag = (fabsf(v0 - 1.0f) < mg) || (fabsf(v1 - 1.0f) < mg);
                    if (flag) {
                        int nn = n + cc;
                        const uint16_t* xr0 = (const uint16_t*)((const __nv_bfloat16*)g_xt4 +
                                              ((size_t)b * N_ + nn) * C_);
                        const uint16_t* xr1 = (const uint16_t*)((const __nv_bfloat16*)g_xt4 +
                                              ((size_t)(B_ + b) * N_ + nn) * C_);
                        float e0 = 0.f, e1 = 0.f;
                        for (int c = 0; c < C_; ++c) {
                            float wv = __ldg(&wrow[c]);
                            if (xr0[c]) e0 += wv;
                            if (xr1[c]) e1 += wv;
                        }
                        y0 = e0 * inv + sh;
                        y1 = e1 * inv + sh;
                        v0 = y0 * 0.5f;
                        sp0 = (v0 >= 1.0f) ? 1.0f : 0.0f;
                        vv = (sp0 != 0.0f) ? 0.0f : v0;
                        v1 = vv + (y1 - vv) * 0.5f;
                    }
                    float sp1 = (v1 >= 1.0f) ? 1.0f : 0.0f;
                    s0v[cc] = sp0;
                    s1v[cc] = sp1;
                    if (MODE == 0) {
                        uint32_t bit = 1u << (g + rr * 8 + ot * 16);
                        if (sp0 != 0.0f) pc[0][nt][cc] |= bit;
                        if (sp1 != 0.0f) pc[1][nt][cc] |= bit;
                    } else {
                        uint32_t bit = 1u << (nt * 8 + la * 2 + cc);
                        if (sp0 != 0.0f) pk[0][ot][rr] |= bit;
                        if (sp1 != 0.0f) pk[1][ot][rr] |= bit;
                    }
                }
                *(float2*)&outp[ro0 + n] = make_float2(s0v[0], s0v[1]);
                *(float2*)&outp[ro1 + n] = make_float2(s1v[0], s1v[1]);
            }
        }
    }

    if (MODE == 0) {
        const int hword = (o0 + wo * 32) >> 5;
#pragma unroll
        for (int t = 0; t < 2; ++t)
#pragma unroll
            for (int nt = 0; nt < 4; ++nt)
#pragma unroll
                for (int cc = 0; cc < 2; ++cc) {
                    uint32_t w = pc[t][nt][cc];
                    w |= __shfl_xor_sync(0xffffffffu, w, 4);
                    w |= __shfl_xor_sync(0xffffffffu, w, 8);
                    w |= __shfl_xor_sync(0xffffffffu, w, 16);
                    if (g == 0) {
                        int n = nbase + nt * 8 + cc;
                        g_qpk[((size_t)(t * B_ + b) * N_ + n) * 8 + hword] = w;
                    }
                }
    } else {
        uint32_t* pko = (widx == 1) ? g_kpk : g_vpk;
        const int nw = (n0 + wn * 32) >> 5;
#pragma unroll
        for (int t = 0; t < 2; ++t)
#pragma unroll
            for (int ot = 0; ot < 2; ++ot)
#pragma unroll
                for (int rr = 0; rr < 2; ++rr) {
                    uint32_t w = pk[t][ot][rr];
                    w |= __shfl_xor_sync(0xffffffffu, w, 1);
                    w |= __shfl_xor_sync(0xffffffffu, w, 2);
                    if (la == 0) {
                        int o = obase + ot * 16 + rr * 8;
                        pko[((size_t)(t * B_ + b) * C_ + o) * 128 + nw] = w;
                    }
                }
    }
}

// ---------------------------------------------------------------------------
// Kernel 3: kv via popcount over packed bits
// ---------------------------------------------------------------------------
__global__ __launch_bounds__(256) void kv_pk_kernel() {
    int h = blockIdx.x, b = blockIdx.y, t = blockIdx.z;
    int tb = t * B_ + b;
    __shared__ uint32_t ks[32 * 129];
    __shared__ uint32_t vs[32 * 129];
    int tid = threadIdx.x;
    const uint32_t* kp = g_kpk + ((size_t)tb * C_ + h * D_) * 128;
    const uint32_t* vp = g_vpk + ((size_t)tb * C_ + h * D_) * 128;
    for (int i = tid; i < 4096; i += 256) {
        int dd = i >> 7, w = i & 127;
        ks[dd * 129 + w] = kp[i];
        vs[dd * 129 + w] = vp[i];
    }
    __syncthreads();
    float* kvout = g_kv + ((size_t)tb * NH_ + h) * (D_ * D_);
    for (int p = tid; p < 1024; p += 256) {
        int dd = p >> 5, e = p & 31;
        const uint32_t* kd = ks + dd * 129;
        const uint32_t* ve = vs + e * 129;
        int acc = 0;
#pragma unroll 8
        for (int w = 0; w < 128; ++w) acc += __popc(kd[w] & ve[w]);
        kvout[p] = (float)acc;
    }
}

// ---------------------------------------------------------------------------
// Kernel 4: attn via masked row-sum, LIF(0.5) -> g_st (bf16 [n,c])
// ---------------------------------------------------------------------------
__global__ __launch_bounds__(256) void attn_pk_kernel() {
    __shared__ float kvs[2][32][33];
    int n0 = blockIdx.x * 128;
    int h = blockIdx.y;
    int b = blockIdx.z;
    int tid = threadIdx.x;

    for (int l = tid; l < 2048; l += 256) {
        int t = l >> 10;
        int r = l & 1023;
        kvs[t][r >> 5][r & 31] = g_kv[((size_t)(t * B_ + b) * NH_ + h) * 1024 + r];
    }
    __syncthreads();

    int nl = tid >> 1;
    int eh = (tid & 1) * 16;
    int nn = n0 + nl;
    uint32_t qw0 = g_qpk[((size_t)b * N_ + nn) * 8 + h];
    uint32_t qw1 = g_qpk[((size_t)(B_ + b) * N_ + nn) * 8 + h];

    float a0[16], a1[16];
#pragma unroll
    for (int j = 0; j < 16; ++j) { a0[j] = 0.f; a1[j] = 0.f; }
#pragma unroll 4
    for (int dd = 0; dd < 32; ++dd) {
        if ((qw0 >> dd) & 1) {
#pragma unroll
            for (int j = 0; j < 16; ++j) a0[j] += kvs[0][dd][eh + j];
        }
        if ((qw1 >> dd) & 1) {
#pragma unroll
            for (int j = 0; j < 16; ++j) a1[j] += kvs[1][dd][eh + j];
        }
    }

    __nv_bfloat16 o0[16], o1[16];
#pragma unroll
    for (int j = 0; j < 16; ++j) {
        float y0 = a0[j] * 0.125f;
        float y1 = a1[j] * 0.125f;
        float v = y0 * 0.5f;
        float t0 = (v >= 0.5f) ? 1.0f : 0.0f;
        if (t0 != 0.0f) v = 0.0f;
        v = v + (y1 - v) * 0.5f;
        float t1 = (v >= 0.5f) ? 1.0f : 0.0f;
        o0[j] = __float2bfloat16(t0);
        o1[j] = __float2bfloat16(t1);
    }
    __nv_bfloat16* stt = (__nv_bfloat16*)g_st4;
    size_t b0 = ((size_t)b * N_ + nn) * C_ + h * D_ + eh;
    size_t b1 = ((size_t)(B_ + b) * N_ + nn) * C_ + h * D_ + eh;
    *(uint4*)&stt[b0] = *(uint4*)&o0[0];
    *(uint4*)&stt[b0 + 8] = *(uint4*)&o0[8];
    *(uint4*)&stt[b1] = *(uint4*)&o1[0];
    *(uint4*)&stt[b1 + 8] = *(uint4*)&o1[8];
}

// ---------------------------------------------------------------------------
// Kernel 5: HMMA projection GEMM: out = BN(Wp @ s + bp). Split hi+lo (exact),
// 3-stage pipeline, bf16 ldmatrix B.
// ---------------------------------------------------------------------------
__global__ __launch_bounds__(256) void hmma_p(
    float* __restrict__ outp, const float* __restrict__ bp,
    const float* __restrict__ gamma, const float* __restrict__ beta,
    const float* __restrict__ mean, const float* __restrict__ var) {
    extern __shared__ __align__(16) char smem[];
    uint32_t sb = smem_u32(smem);
    const int tid = threadIdx.x;
    const int lane = tid & 31;
    const int wid = tid >> 5;
    const int wo = wid >> 2;
    const int wn = wid & 3;
    const int n0 = blockIdx.x * 128;
    const int o0 = blockIdx.y * 64;
    const int z  = blockIdx.z;

    const __nv_bfloat16* wh = (const __nv_bfloat16*)g_whi4 + 3 * 65536 + o0 * C_;
    const __nv_bfloat16* wl = (const __nv_bfloat16*)g_wlo4 + 3 * 65536 + o0 * C_;
    const __nv_bfloat16* xg = (const __nv_bfloat16*)g_st4 + ((size_t)z * N_ + n0) * C_;

    float d[2][4][4];
#pragma unroll
    for (int a = 0; a < 2; a++)
#pragma unroll
        for (int c = 0; c < 4; c++)
#pragma unroll
            for (int j = 0; j < 4; j++) d[a][c][j] = 0.f;

    const int lr = tid >> 2;
    const int lj = tid & 3;
    auto load_chunk = [&](int c0, int stg) {
        uint32_t s0 = sb + (uint32_t)stg * SSTG_P;
        cp16(s0 + WH_OFF + lr * 80 + lj * 16, wh + (size_t)lr * C_ + c0 + lj * 8);
        cp16(s0 + WL_OFF + lr * 80 + lj * 16, wl + (size_t)lr * C_ + c0 + lj * 8);
        cp16(s0 + X0_OFF + lr * 80 + lj * 16, xg + (size_t)lr * C_ + c0 + lj * 8);
        cp16(s0 + X0_OFF + (64 + lr) * 80 + lj * 16, xg + (size_t)(64 + lr) * C_ + c0 + lj * 8);
    };

    load_chunk(0, 0);
    CP_COMMIT();
    load_chunk(32, 1);
    CP_COMMIT();

    const int arow = (lane & 7) + ((lane >> 3) & 1) * 8;
    const int acol = ((lane >> 4) & 1) * 16;
    const int brow = (lane & 7) + ((lane >> 4) & 1) * 8;
    const int bcol = ((lane >> 3) & 1) * 16;

#pragma unroll
    for (int ch = 0; ch < 8; ++ch) {
        if (ch < 7) { CP_WAIT1(); } else { CP_WAIT0(); }
        __syncthreads();
        if (ch + 2 < 8) {
            load_chunk((ch + 2) * 32, (ch + 2) % 3);
            CP_COMMIT();
        }
        uint32_t s0 = sb + (uint32_t)(ch % 3) * SSTG_P;
        uint32_t aW = s0 + WH_OFF + (wo * 32) * 80;
        uint32_t aX = s0 + X0_OFF + (wn * 32) * 80;
#pragma unroll
        for (int k16 = 0; k16 < 2; ++k16) {
            int kb = k16 * 32;
            uint32_t ah[2][4], al[2][4];
#pragma unroll
            for (int ot = 0; ot < 2; ++ot) {
                uint32_t ad = aW + (uint32_t)(ot * 16 + arow) * 80 + kb + acol;
                ldm4(ah[ot], ad);
                ldm4(al[ot], ad + (WL_OFF - WH_OFF));
            }
            uint32_t bf[4][2];
#pragma unroll
            for (int ns = 0; ns < 2; ++ns) {
                uint32_t r[4];
                ldm4(r, aX + (uint32_t)(ns * 16 + brow) * 80 + kb + bcol);
                bf[ns * 2][0] = r[0];
                bf[ns * 2][1] = r[1];
                bf[ns * 2 + 1][0] = r[2];
                bf[ns * 2 + 1][1] = r[3];
            }
#pragma unroll
            for (int ot = 0; ot < 2; ++ot)
#pragma unroll
                for (int nt = 0; nt < 4; ++nt) {
                    mma16816(d[ot][nt], ah[ot], bf[nt]);
                    mma16816(d[ot][nt], al[ot], bf[nt]);
                }
        }
    }

    const int obase = o0 + wo * 32 + (lane >> 2);
    const int nbase = n0 + wn * 32 + 2 * (lane & 3);
#pragma unroll
    for (int ot = 0; ot < 2; ++ot) {
#pragma unroll
        for (int rr = 0; rr < 2; ++rr) {
            int o = obase + ot * 16 + rr * 8;
            float g  = __ldg(&gamma[o]);
            float sq = sqrtf(__ldg(&var[o]) + 1e-5f);
            float inv = g / sq;
            float sh  = __ldg(&beta[o]) - __ldg(&mean[o]) * g / sq;
            float bb  = __ldg(&bp[o]);
            size_t ro = ((size_t)z * C_ + o) * N_;
#pragma unroll
            for (int nt = 0; nt < 4; ++nt) {
                int n = nbase + nt * 8;
                float y0 = (d[ot][nt][rr * 2 + 0] + bb) * inv + sh;
                float y1 = (d[ot][nt][rr * 2 + 1] + bb) * inv + sh;
                *(float2*)&outp[ro + n] = make_float2(y0, y1);
            }
        }
    }
}

// ---------------------------------------------------------------------------
extern "C" void kernel_launch(void* const* d_in, const int* in_sizes, int n_in,
                              void* d_out, int out_size) {
    const float* x  = (const float*)d_in[0];
    const float* wq = (const float*)d_in[1];
    const float* wk = (const float*)d_in[2];
    const float* wv = (const float*)d_in[3];
    const float* wp = (const float*)d_in[4];
    const float* bp = (const float*)d_in[5];
    const float* qg = (const float*)d_in[6];
    const float* qb = (const float*)d_in[7];
    const float* qm = (const float*)d_in[8];
    const float* qv = (const float*)d_in[9];
    const float* kg = (const float*)d_in[10];
    const float* kb = (const float*)d_in[11];
    const float* km = (const float*)d_in[12];
    const float* kv_ = (const float*)d_in[13];
    const float* vg = (const float*)d_in[14];
    const float* vb = (const float*)d_in[15];
    const float* vm = (const float*)d_in[16];
    const float* vv = (const float*)d_in[17];
    const float* pg = (const float*)d_in[18];
    const float* pb = (const float*)d_in[19];
    const float* pm = (const float*)d_in[20];
    const float* pv = (const float*)d_in[21];

    float* out = (float*)d_out;
    float* xs = out + (size_t)SZ;
    float* qo = out + 2 * (size_t)SZ;
    float* ko = out + 3 * (size_t)SZ;
    float* vo = out + 4 * (size_t)SZ;

    cudaFuncSetAttribute(hmma_qkv<0>, cudaFuncAttributeMaxDynamicSharedMemorySize, 3 * SSTG_Q);
    cudaFuncSetAttribute(hmma_qkv<1>, cudaFuncAttributeMaxDynamicSharedMemorySize, 3 * SSTG_Q);
    cudaFuncSetAttribute(hmma_p, cudaFuncAttributeMaxDynamicSharedMemorySize, 3 * SSTG_P);

    // 0) weight split
    split_w_kernel<<<1024, 256>>>(wq, wk, wv, wp);

    // 1) input LIF -> xs (fp32) + transposed bf16 activations
    lif_x_t_kernel<<<dim3(N_ / 64, C_ / 64, B_), 256>>>(x, xs);

    // 2) q/k/v HMMA GEMM (hi-only + exact margin correction) + BN + LIF
    dim3 gg(N_ / 128, C_ / 64, B_);
    hmma_qkv<0><<<gg, 256, 3 * SSTG_Q>>>(0, wq, qo, qg, qb, qm, qv);
    hmma_qkv<1><<<gg, 256, 3 * SSTG_Q>>>(1, wk, ko, kg, kb, km, kv_);
    hmma_qkv<1><<<gg, 256, 3 * SSTG_Q>>>(2, wv, vo, vg, vb, vm, vv);

    // 3) kv via popcount
    kv_pk_kernel<<<dim3(NH_, B_, T_), 256>>>();

    // 4) attn via masked row-sum + LIF(0.5) -> bf16 spikes
    attn_pk_kernel<<<dim3(N_ / 128, NH_, B_), 256>>>();

    // 5) projection HMMA GEMM (split, exact) + bias + BN -> out
    hmma_p<<<dim3(N_ / 128, C_ / 64, T_ * B_), 256, 3 * SSTG_P>>>(
        out, bp, pg, pb, pm, pv);
}